// round 3
// baseline (speedup 1.0000x reference)
#include <cuda_runtime.h>
#include <math.h>

#define D_MODEL 1024
#define NHEAD   16
#define HDIM    64
#define BATCH   4
#define SEQ     2048
#define FFN_DIM 4096
#define ROWS    (BATCH * SEQ)   /* 8192 */

/* ------------------------------------------------------------------ */
/* Scratch: __device__ globals (no cudaMalloc allowed)                 */
/* ------------------------------------------------------------------ */
__device__ float g_xn  [ROWS * D_MODEL];   /* LN output (reused for LN2) */
__device__ float g_q   [ROWS * D_MODEL];   /* [B,H,L,HD] */
__device__ float g_k   [ROWS * D_MODEL];
__device__ float g_v   [ROWS * D_MODEL];
__device__ float g_attn[ROWS * D_MODEL];   /* [B,L,D] */
__device__ float g_x1  [ROWS * D_MODEL];   /* residual after attention */
__device__ float g_h   [ROWS * FFN_DIM];   /* FFN hidden */

/* ------------------------------------------------------------------ */
/* LayerNorm: one block per row, 256 threads, float4                   */
/* ------------------------------------------------------------------ */
__global__ __launch_bounds__(256)
void ln_kernel(const float* __restrict__ x, const float* __restrict__ g,
               const float* __restrict__ be, float* __restrict__ out)
{
    __shared__ float sh[16];
    const int row = blockIdx.x;
    const int t   = threadIdx.x;
    const float4* xr = (const float4*)(x + (size_t)row * D_MODEL);
    float4 v = xr[t];
    float s  = v.x + v.y + v.z + v.w;
    float s2 = v.x*v.x + v.y*v.y + v.z*v.z + v.w*v.w;
#pragma unroll
    for (int o = 16; o > 0; o >>= 1) {
        s  += __shfl_xor_sync(0xffffffffu, s,  o);
        s2 += __shfl_xor_sync(0xffffffffu, s2, o);
    }
    if ((t & 31) == 0) { sh[t >> 5] = s; sh[8 + (t >> 5)] = s2; }
    __syncthreads();
    float ts = 0.f, ts2 = 0.f;
#pragma unroll
    for (int w = 0; w < 8; w++) { ts += sh[w]; ts2 += sh[8 + w]; }
    const float mean = ts * (1.0f / 1024.0f);
    const float var  = ts2 * (1.0f / 1024.0f) - mean * mean;
    const float inv  = rsqrtf(var + 1e-5f);
    float4 gg = ((const float4*)g)[t];
    float4 bb = ((const float4*)be)[t];
    float4 o;
    o.x = (v.x - mean) * inv * gg.x + bb.x;
    o.y = (v.y - mean) * inv * gg.y + bb.y;
    o.z = (v.z - mean) * inv * gg.z + bb.z;
    o.w = (v.w - mean) * inv * gg.w + bb.w;
    ((float4*)(out + (size_t)row * D_MODEL))[t] = o;
}

/* ------------------------------------------------------------------ */
/* SGEMM: C = A[M,K] @ B[K,N] + bias (+resid) (relu) (qkv-permute)     */
/* 128x128 tile, BK=8, 256 threads, 8x8 per thread                     */
/* ------------------------------------------------------------------ */
template<bool QKV_STORE, bool RELU, bool RESID>
__global__ __launch_bounds__(256)
void sgemm_kernel(const float* __restrict__ A, const float* __restrict__ B,
                  const float* __restrict__ bias, const float* __restrict__ resid,
                  float* __restrict__ C, int M, int N, int K)
{
    __shared__ float As[8][128];
    __shared__ float Bs[8][128];
    const int tid  = threadIdx.x;
    const int tx   = tid & 15, ty = tid >> 4;
    const int row0 = blockIdx.y << 7, col0 = blockIdx.x << 7;

    float acc[8][8];
#pragma unroll
    for (int i = 0; i < 8; i++)
#pragma unroll
        for (int j = 0; j < 8; j++) acc[i][j] = 0.f;

    const int arow = tid >> 1;
    const int akq  = (tid & 1) << 2;
    const int brow = tid >> 5;
    const int bcol = (tid & 31) << 2;
    const float* Ap = A + (size_t)(row0 + arow) * K + akq;
    const float* Bp = B + (size_t)brow * N + col0 + bcol;

    for (int kt = 0; kt < K; kt += 8) {
        float4 av = *(const float4*)(Ap + kt);
        float4 bv = *(const float4*)(Bp + (size_t)kt * N);
        __syncthreads();
        As[akq + 0][arow] = av.x;
        As[akq + 1][arow] = av.y;
        As[akq + 2][arow] = av.z;
        As[akq + 3][arow] = av.w;
        *(float4*)&Bs[brow][bcol] = bv;
        __syncthreads();
#pragma unroll
        for (int kk = 0; kk < 8; kk++) {
            float a[8], b[8];
            *(float4*)&a[0] = *(const float4*)&As[kk][ty << 2];
            *(float4*)&a[4] = *(const float4*)&As[kk][64 + (ty << 2)];
            *(float4*)&b[0] = *(const float4*)&Bs[kk][tx << 2];
            *(float4*)&b[4] = *(const float4*)&Bs[kk][64 + (tx << 2)];
#pragma unroll
            for (int i = 0; i < 8; i++)
#pragma unroll
                for (int j = 0; j < 8; j++)
                    acc[i][j] = fmaf(a[i], b[j], acc[i][j]);
        }
    }

    float bvals[8];
    *(float4*)&bvals[0] = *(const float4*)&bias[col0 + (tx << 2)];
    *(float4*)&bvals[4] = *(const float4*)&bias[col0 + 64 + (tx << 2)];

#pragma unroll
    for (int ig = 0; ig < 2; ig++) {
#pragma unroll
        for (int i = 0; i < 4; i++) {
            const int r = row0 + ig * 64 + (ty << 2) + i;
#pragma unroll
            for (int jg = 0; jg < 2; jg++) {
                const int cb = col0 + jg * 64 + (tx << 2);
                float4 val;
                val.x = acc[ig * 4 + i][jg * 4 + 0] + bvals[jg * 4 + 0];
                val.y = acc[ig * 4 + i][jg * 4 + 1] + bvals[jg * 4 + 1];
                val.z = acc[ig * 4 + i][jg * 4 + 2] + bvals[jg * 4 + 2];
                val.w = acc[ig * 4 + i][jg * 4 + 3] + bvals[jg * 4 + 3];
                if (RESID) {
                    float4 rv = *(const float4*)&resid[(size_t)r * N + cb];
                    val.x += rv.x; val.y += rv.y; val.z += rv.z; val.w += rv.w;
                }
                if (RELU) {
                    val.x = fmaxf(val.x, 0.f); val.y = fmaxf(val.y, 0.f);
                    val.z = fmaxf(val.z, 0.f); val.w = fmaxf(val.w, 0.f);
                }
                if (QKV_STORE) {
                    const int b_  = r >> 11, l_ = r & (SEQ - 1);
                    const int h_  = cb >> 6, hd_ = cb & 63;
                    *(float4*)&C[(((size_t)(b_ * NHEAD + h_) * SEQ) + l_) * HDIM + hd_] = val;
                } else {
                    *(float4*)&C[(size_t)r * N + cb] = val;
                }
            }
        }
    }
}

/* ------------------------------------------------------------------ */
/* Causal flash attention, fp32, 64x64 tiles, fused rel_pos_bias       */
/* grid: (SEQ/64 q-tiles, B*H), 256 threads, dynamic smem              */
/* ------------------------------------------------------------------ */
#define FL_SMEM_FLOATS (3 * 64 * 65 + 64 * 64)
#define FL_SMEM_BYTES  (FL_SMEM_FLOATS * 4)

__global__ __launch_bounds__(256)
void flash_kernel(const float* __restrict__ Qg, const float* __restrict__ Kg,
                  const float* __restrict__ Vg, const float* __restrict__ Bg,
                  float* __restrict__ Og)
{
    extern __shared__ float smem[];
    float (*Qs)[65] = (float(*)[65]) smem;
    float (*Ks)[65] = (float(*)[65])(smem + 64 * 65);
    float (*Ps)[65] = (float(*)[65])(smem + 2 * 64 * 65);
    float (*Vs)[64] = (float(*)[64])(smem + 3 * 64 * 65);

    const int tid = threadIdx.x;
    const int tx  = tid & 15, ty = tid >> 4;
    const int bh  = blockIdx.y;
    const int h   = bh & (NHEAD - 1);
    const int b   = bh >> 4;
    /* reversed: heavy (long-causal) tiles launch first for wave balance */
    const int qt  = gridDim.x - 1 - blockIdx.x;
    const int q0  = qt << 6;

    const float* Qp = Qg + ((size_t)bh * SEQ + q0) * HDIM;
    const float* Kp = Kg + (size_t)bh * SEQ * HDIM;
    const float* Vp = Vg + (size_t)bh * SEQ * HDIM;
    const float* Bp = Bg + (size_t)h * SEQ * SEQ;

    /* load Q tile */
    for (int i = tid; i < 1024; i += 256) {
        const int r = i >> 4, s = (i & 15) << 2;
        float4 qv = *(const float4*)(Qp + r * HDIM + s);
        Qs[r][s] = qv.x; Qs[r][s + 1] = qv.y; Qs[r][s + 2] = qv.z; Qs[r][s + 3] = qv.w;
    }

    float m_i[4], l_i[4], oacc[4][4];
#pragma unroll
    for (int i = 0; i < 4; i++) {
        m_i[i] = -1e30f; l_i[i] = 0.f;
#pragma unroll
        for (int j = 0; j < 4; j++) oacc[i][j] = 0.f;
    }

    const float scale = 0.125f;   /* HD^-0.5 */
    const int ntiles = qt + 1;

    for (int kt = 0; kt < ntiles; kt++) {
        const int k0 = kt << 6;
        __syncthreads();
        for (int i = tid; i < 1024; i += 256) {
            const int r = i >> 4, s = (i & 15) << 2;
            float4 kv = *(const float4*)(Kp + (size_t)(k0 + r) * HDIM + s);
            Ks[r][s] = kv.x; Ks[r][s + 1] = kv.y; Ks[r][s + 2] = kv.z; Ks[r][s + 3] = kv.w;
            float4 vv = *(const float4*)(Vp + (size_t)(k0 + r) * HDIM + s);
            *(float4*)&Vs[r][s] = vv;
        }
        __syncthreads();

        /* S = Q @ K^T */
        float sv[4][4];
#pragma unroll
        for (int i = 0; i < 4; i++)
#pragma unroll
            for (int j = 0; j < 4; j++) sv[i][j] = 0.f;
#pragma unroll 8
        for (int d = 0; d < 64; d++) {
            float qf[4], kf[4];
#pragma unroll
            for (int i = 0; i < 4; i++) qf[i] = Qs[(ty << 2) + i][d];
#pragma unroll
            for (int j = 0; j < 4; j++) kf[j] = Ks[(tx << 2) + j][d];
#pragma unroll
            for (int i = 0; i < 4; i++)
#pragma unroll
                for (int j = 0; j < 4; j++)
                    sv[i][j] = fmaf(qf[i], kf[j], sv[i][j]);
        }

        /* scale + bias + causal mask, then online softmax */
#pragma unroll
        for (int i = 0; i < 4; i++) {
            const int qi = q0 + (ty << 2) + i;
            float4 bvv = *(const float4*)(Bp + (size_t)qi * SEQ + k0 + (tx << 2));
            float bb[4] = {bvv.x, bvv.y, bvv.z, bvv.w};
#pragma unroll
            for (int j = 0; j < 4; j++) {
                const int kj = k0 + (tx << 2) + j;
                sv[i][j] = (kj <= qi) ? fmaf(sv[i][j], scale, bb[j]) : -1e30f;
            }
        }

#pragma unroll
        for (int i = 0; i < 4; i++) {
            float rmax = fmaxf(fmaxf(sv[i][0], sv[i][1]), fmaxf(sv[i][2], sv[i][3]));
#pragma unroll
            for (int o = 8; o > 0; o >>= 1)
                rmax = fmaxf(rmax, __shfl_xor_sync(0xffffffffu, rmax, o, 16));
            const float mnew = fmaxf(m_i[i], rmax);
            const float corr = __expf(m_i[i] - mnew);
            float rsum = 0.f;
#pragma unroll
            for (int j = 0; j < 4; j++) {
                sv[i][j] = __expf(sv[i][j] - mnew);
                rsum += sv[i][j];
            }
#pragma unroll
            for (int o = 8; o > 0; o >>= 1)
                rsum += __shfl_xor_sync(0xffffffffu, rsum, o, 16);
            l_i[i] = l_i[i] * corr + rsum;
            m_i[i] = mnew;
#pragma unroll
            for (int j = 0; j < 4; j++) oacc[i][j] *= corr;
#pragma unroll
            for (int j = 0; j < 4; j++)
                Ps[(ty << 2) + i][(tx << 2) + j] = sv[i][j];
        }
        __syncthreads();

        /* O += P @ V */
#pragma unroll 8
        for (int c = 0; c < 64; c++) {
            float pf[4];
#pragma unroll
            for (int i = 0; i < 4; i++) pf[i] = Ps[(ty << 2) + i][c];
            float4 vf = *(const float4*)&Vs[c][tx << 2];
#pragma unroll
            for (int i = 0; i < 4; i++) {
                oacc[i][0] = fmaf(pf[i], vf.x, oacc[i][0]);
                oacc[i][1] = fmaf(pf[i], vf.y, oacc[i][1]);
                oacc[i][2] = fmaf(pf[i], vf.z, oacc[i][2]);
                oacc[i][3] = fmaf(pf[i], vf.w, oacc[i][3]);
            }
        }
    }

    /* epilogue: out[b][l][h*64+hd] = O / l */
#pragma unroll
    for (int i = 0; i < 4; i++) {
        const int qi = q0 + (ty << 2) + i;
        const float inv = 1.0f / l_i[i];
        float4 ov;
        ov.x = oacc[i][0] * inv; ov.y = oacc[i][1] * inv;
        ov.z = oacc[i][2] * inv; ov.w = oacc[i][3] * inv;
        *(float4*)&Og[((size_t)b * SEQ + qi) * D_MODEL + h * HDIM + (tx << 2)] = ov;
    }
}

/* ------------------------------------------------------------------ */
/* Host launcher                                                       */
/* ------------------------------------------------------------------ */
extern "C" void kernel_launch(void* const* d_in, const int* in_sizes, int n_in,
                              void* d_out, int out_size)
{
    (void)in_sizes; (void)n_in; (void)out_size;
    const float* x    = (const float*)d_in[0];
    const float* relb = (const float*)d_in[1];
    const float* wq   = (const float*)d_in[2];
    const float* bq   = (const float*)d_in[3];
    const float* wk   = (const float*)d_in[4];
    const float* bk   = (const float*)d_in[5];
    const float* wv   = (const float*)d_in[6];
    const float* bv   = (const float*)d_in[7];
    const float* wo   = (const float*)d_in[8];
    const float* bo   = (const float*)d_in[9];
    const float* g1   = (const float*)d_in[10];
    const float* be1  = (const float*)d_in[11];
    const float* g2   = (const float*)d_in[12];
    const float* be2  = (const float*)d_in[13];
    const float* w1   = (const float*)d_in[14];
    const float* bf1  = (const float*)d_in[15];
    const float* w2   = (const float*)d_in[16];
    const float* bf2  = (const float*)d_in[17];
    float* out = (float*)d_out;

    float *xn, *q, *k, *v, *attn, *x1, *hbuf;
    cudaGetSymbolAddress((void**)&xn,   g_xn);
    cudaGetSymbolAddress((void**)&q,    g_q);
    cudaGetSymbolAddress((void**)&k,    g_k);
    cudaGetSymbolAddress((void**)&v,    g_v);
    cudaGetSymbolAddress((void**)&attn, g_attn);
    cudaGetSymbolAddress((void**)&x1,   g_x1);
    cudaGetSymbolAddress((void**)&hbuf, g_h);

    cudaFuncSetAttribute(flash_kernel,
                         cudaFuncAttributeMaxDynamicSharedMemorySize, FL_SMEM_BYTES);

    const dim3 gd1024(D_MODEL / 128, ROWS / 128);  /* (8, 64)  */
    const dim3 gd4096(FFN_DIM / 128, ROWS / 128);  /* (32, 64) */

    /* LN1 */
    ln_kernel<<<ROWS, 256>>>(x, g1, be1, xn);
    /* QKV projections (fused bias + [B,H,L,HD] permute) */
    sgemm_kernel<true,  false, false><<<gd1024, 256>>>(xn, wq, bq, nullptr, q,    ROWS, D_MODEL, D_MODEL);
    sgemm_kernel<true,  false, false><<<gd1024, 256>>>(xn, wk, bk, nullptr, k,    ROWS, D_MODEL, D_MODEL);
    sgemm_kernel<true,  false, false><<<gd1024, 256>>>(xn, wv, bv, nullptr, v,    ROWS, D_MODEL, D_MODEL);
    /* causal flash attention with fused rel_pos_bias */
    flash_kernel<<<dim3(SEQ / 64, BATCH * NHEAD), 256, FL_SMEM_BYTES>>>(q, k, v, relb, attn);
    /* O projection + residual(x) */
    sgemm_kernel<false, false, true ><<<gd1024, 256>>>(attn, wo, bo, x,  x1,  ROWS, D_MODEL, D_MODEL);
    /* LN2 */
    ln_kernel<<<ROWS, 256>>>(x1, g2, be2, xn);
    /* FFN1 + ReLU */
    sgemm_kernel<false, true,  false><<<gd4096, 256>>>(xn, w1, bf1, nullptr, hbuf, ROWS, FFN_DIM, D_MODEL);
    /* FFN2 + residual(x1) -> out */
    sgemm_kernel<false, false, true ><<<gd1024, 256>>>(hbuf, w2, bf2, x1, out, ROWS, D_MODEL, FFN_DIM);
}